// round 1
// baseline (speedup 1.0000x reference)
#include <cuda_runtime.h>
#include <cstdint>

// SqueezeLayer: checkerboard space-to-depth.
// out[b, 4c + 2*kh + kw, h2, w2] = x[b, c, 2*h2 + kh, 2*w2 + kw]
// Shapes: x (8, 64, 512, 512) f32 -> out (8, 256, 256, 256) f32.
//
// Strategy: each thread loads one float4 (4 consecutive floats of one input
// row). Elements {.x,.z} are the even (kw=0) lane pair -> one float2 store;
// {.y,.w} are the odd (kw=1) pair -> a second float2 store. Both stores are
// contiguous across a warp => fully coalesced reads and writes.

static constexpr int B  = 8;
static constexpr int C  = 64;
static constexpr int H  = 512;
static constexpr int W  = 512;
static constexpr int H2 = H / 2;   // 256
static constexpr int W2 = W / 2;   // 256
static constexpr int T_PER_ROW = W / 4;        // 128 float4s per input row
static constexpr long long TOTAL_T = (long long)B * C * H * T_PER_ROW; // 33,554,432

__global__ void squeeze_kernel(const float4* __restrict__ in4,
                               float2* __restrict__ out2) {
    unsigned tid = blockIdx.x * blockDim.x + threadIdx.x;  // fits in 32 bits (33.5M)

    // Decompose: tid = ((bc * H) + h) * T_PER_ROW + t
    unsigned t  = tid & (T_PER_ROW - 1);      // % 128
    unsigned r  = tid >> 7;                   // / 128
    unsigned h  = r & (H - 1);                // % 512
    unsigned bc = r >> 9;                     // / 512   (= b*C + c)

    unsigned kh = h & 1;
    unsigned h2 = h >> 1;

    float4 v = in4[tid];   // in[b, c, h, 4t .. 4t+3]

    // Output channel linear index: b*(4C) + 4c + 2*kh  (== bc*4 + 2*kh since 4C=256)
    unsigned outCh = (bc << 2) + (kh << 1);

    // float offset of out[outCh, h2, 2t]; as float2 index divide by 2.
    // (outCh*H2 + h2)*W2 + 2t   -> float2 idx = ((outCh*H2 + h2)*W2)/2 + t
    unsigned base2 = ((outCh * H2 + h2) * (W2 / 2)) + t;

    // kw = 0 channel: even elements
    out2[base2] = make_float2(v.x, v.z);
    // kw = 1 channel: odd elements (next channel => + H2*W2 floats => + H2*W2/2 float2)
    out2[base2 + (H2 * W2 / 2)] = make_float2(v.y, v.w);
}

extern "C" void kernel_launch(void* const* d_in, const int* in_sizes, int n_in,
                              void* d_out, int out_size) {
    const float4* in4 = (const float4*)d_in[0];
    float2* out2 = (float2*)d_out;

    const int threads = 256;
    const long long blocks = (TOTAL_T + threads - 1) / threads;  // 131072
    squeeze_kernel<<<(unsigned)blocks, threads>>>(in4, out2);
}

// round 2
// speedup vs baseline: 1.0100x; 1.0100x over previous
#include <cuda_runtime.h>
#include <cstdint>

// SqueezeLayer: checkerboard space-to-depth.
// out[b, 4c + 2*kh + kw, h2, w2] = x[b, c, 2*h2 + kh, 2*w2 + kw]
// Shapes: x (8, 64, 512, 512) f32 -> out (8, 256, 256, 256) f32.
//
// R1: each thread handles 8 consecutive floats of one input row
// (2x LDG.128), de-interleaves into two float4s (even lanes -> kw=0 channel,
// odd lanes -> kw=1 channel), stored with 2x STG.128. Streaming cache hints
// (__ldcs/__stcs) since no data is ever re-touched.

static constexpr int B  = 8;
static constexpr int C  = 64;
static constexpr int H  = 512;
static constexpr int W  = 512;
static constexpr int H2 = H / 2;   // 256
static constexpr int W2 = W / 2;   // 256
static constexpr int T_PER_ROW = W / 8;        // 64 threads per input row (8 floats each)
static constexpr long long TOTAL_T = (long long)B * C * H * T_PER_ROW; // 16,777,216

__global__ void squeeze_kernel(const float4* __restrict__ in4,
                               float4* __restrict__ out4) {
    unsigned tid = blockIdx.x * blockDim.x + threadIdx.x;  // < 16.8M

    // Decompose: tid = ((bc * H) + h) * T_PER_ROW + t
    unsigned t  = tid & (T_PER_ROW - 1);      // % 64
    unsigned r  = tid >> 6;                   // / 64
    unsigned h  = r & (H - 1);                // % 512
    unsigned bc = r >> 9;                     // / 512   (= b*C + c)

    unsigned kh = h & 1;
    unsigned h2 = h >> 1;

    // Two consecutive float4s: input floats [8t .. 8t+7] of row (bc, h)
    unsigned inBase = (r << 7) + (t << 1);    // r*128 + 2t (float4 units)
    float4 v0 = __ldcs(&in4[inBase]);
    float4 v1 = __ldcs(&in4[inBase + 1]);

    // Output channel linear index: bc*4 + 2*kh  (4C == 256 so b folds in)
    unsigned outCh = (bc << 2) + (kh << 1);

    // float4 offset of out[outCh, h2, 8t/2]: ((outCh*H2 + h2)*W2)/4 + t
    unsigned base4 = (outCh * H2 + h2) * (W2 / 4) + t;

    // kw = 0 channel: even input elements
    __stcs(&out4[base4], make_float4(v0.x, v0.z, v1.x, v1.z));
    // kw = 1 channel: odd input elements (next channel => + H2*W2/4 float4s)
    __stcs(&out4[base4 + (H2 * W2 / 4)], make_float4(v0.y, v0.w, v1.y, v1.w));
}

extern "C" void kernel_launch(void* const* d_in, const int* in_sizes, int n_in,
                              void* d_out, int out_size) {
    const float4* in4 = (const float4*)d_in[0];
    float4* out4 = (float4*)d_out;

    const int threads = 256;
    const long long blocks = (TOTAL_T + threads - 1) / threads;  // 65536
    squeeze_kernel<<<(unsigned)blocks, threads>>>(in4, out4);
}